// round 1
// baseline (speedup 1.0000x reference)
#include <cuda_runtime.h>
#include <math.h>

#define B_  4
#define T_  2305
#define C_  384
#define H_  6
#define DH  64
#define HW  48
#define M_  (B_*T_)          // 9220 rows
#define BN_EPS 1e-5f

// ---------------- device scratch (no allocations allowed) ----------------
__device__ float g_qin[M_*C_];
__device__ float g_kin[M_*C_];
__device__ float g_vin[M_*C_];
__device__ float g_q  [M_*C_];   // (b,h,t,d)
__device__ float g_k  [M_*C_];
__device__ float g_v  [M_*C_];
__device__ float g_att[M_*C_];   // (b,t,c)

// ---------------- kernel 1: depthwise conv 3x3 + BN for q,k,v ----------------
__global__ void prep_kernel(const float* __restrict__ x,
    const float* __restrict__ kq, const float* __restrict__ kk,
    const float* __restrict__ kv,
    const float* __restrict__ gq, const float* __restrict__ bq,
    const float* __restrict__ mq, const float* __restrict__ vq,
    const float* __restrict__ gk, const float* __restrict__ bk,
    const float* __restrict__ mk, const float* __restrict__ vk,
    const float* __restrict__ gv, const float* __restrict__ bv,
    const float* __restrict__ mv, const float* __restrict__ vv)
{
    int idx = blockIdx.x*blockDim.x + threadIdx.x;
    if (idx >= M_*C_) return;
    int c = idx % C_;
    int t = (idx / C_) % T_;
    int b = idx / (C_*T_);
    const float* xb = x + (size_t)b*T_*C_;
    if (t == 0) {                       // cls token passes through
        float v = xb[c];
        g_qin[idx] = v; g_kin[idx] = v; g_vin[idx] = v;
        return;
    }
    int p = t - 1, py = p / HW, px = p % HW;
    float aq = 0.f, ak = 0.f, av = 0.f;
    #pragma unroll
    for (int dy = 0; dy < 3; dy++) {
        int ny = py + dy - 1;
        if ((unsigned)ny >= (unsigned)HW) continue;
        #pragma unroll
        for (int dx = 0; dx < 3; dx++) {
            int nx = px + dx - 1;
            if ((unsigned)nx >= (unsigned)HW) continue;
            float xv = xb[(size_t)(1 + ny*HW + nx)*C_ + c];
            int tap = dy*3 + dx;
            aq = fmaf(xv, kq[c*9 + tap], aq);
            ak = fmaf(xv, kk[c*9 + tap], ak);
            av = fmaf(xv, kv[c*9 + tap], av);
        }
    }
    g_qin[idx] = (aq - mq[c]) * (gq[c]*rsqrtf(vq[c]+BN_EPS)) + bq[c];
    g_kin[idx] = (ak - mk[c]) * (gk[c]*rsqrtf(vk[c]+BN_EPS)) + bk[c];
    g_vin[idx] = (av - mv[c]) * (gv[c]*rsqrtf(vv[c]+BN_EPS)) + bv[c];
}

// ---------------- kernel 2/4: tiled SGEMM  D[m,n] = sum_k A[m,k]*W[n,k] ----------------
// BM=BN=64, BK=16, 256 threads, 4x4 micro-tile.
// HEAD_OUT: scatter into (b,h,t,d) layout; else row-major + bias.
template<bool HEAD_OUT>
__global__ void __launch_bounds__(256) gemm64(const float* __restrict__ A,
                                              const float* __restrict__ W,
                                              const float* __restrict__ bias,
                                              float* __restrict__ D)
{
    __shared__ float sA[16][68];    // [k][m]
    __shared__ float sB[16][68];    // [k][n]
    int m0 = blockIdx.x * 64, n0 = blockIdx.y * 64;
    int tid = threadIdx.x;
    int tx = tid & 15, ty = tid >> 4;
    int lr = tid >> 2, lc = (tid & 3) * 4;
    float acc[4][4] = {};
    for (int k0 = 0; k0 < C_; k0 += 16) {
        float4 a4 = make_float4(0.f,0.f,0.f,0.f);
        int gm = m0 + lr;
        if (gm < M_) a4 = *(const float4*)(A + (size_t)gm*C_ + k0 + lc);
        sA[lc+0][lr] = a4.x; sA[lc+1][lr] = a4.y; sA[lc+2][lr] = a4.z; sA[lc+3][lr] = a4.w;
        float4 b4 = *(const float4*)(W + (size_t)(n0 + lr)*C_ + k0 + lc);
        sB[lc+0][lr] = b4.x; sB[lc+1][lr] = b4.y; sB[lc+2][lr] = b4.z; sB[lc+3][lr] = b4.w;
        __syncthreads();
        #pragma unroll
        for (int kk = 0; kk < 16; kk++) {
            float4 av = *(const float4*)&sA[kk][4*ty];
            float4 bv = *(const float4*)&sB[kk][4*tx];
            float ar[4] = {av.x, av.y, av.z, av.w};
            float br[4] = {bv.x, bv.y, bv.z, bv.w};
            #pragma unroll
            for (int i = 0; i < 4; i++)
                #pragma unroll
                for (int j = 0; j < 4; j++)
                    acc[i][j] = fmaf(ar[i], br[j], acc[i][j]);
        }
        __syncthreads();
    }
    #pragma unroll
    for (int i = 0; i < 4; i++) {
        int gm = m0 + 4*ty + i;
        if (gm >= M_) continue;
        #pragma unroll
        for (int j = 0; j < 4; j++) {
            int gn = n0 + 4*tx + j;
            float v = acc[i][j];
            if (HEAD_OUT) {
                int b = gm / T_, t = gm % T_;
                int h = gn >> 6, d = gn & 63;
                D[(((size_t)b*H_ + h)*T_ + t)*DH + d] = v;
            } else {
                D[(size_t)gm*C_ + gn] = v + bias[gn];
            }
        }
    }
}

// ---------------- kernel 3: flash attention, 64-query CTA, 64-key tiles ----------------
#define ATTN_SMEM (4*64*68*4)
__global__ void __launch_bounds__(256) attn_kernel(const float* __restrict__ Qh,
                                                   const float* __restrict__ Kh,
                                                   const float* __restrict__ Vh,
                                                   float* __restrict__ Oa)
{
    extern __shared__ float sm[];
    float* sQ = sm;             // [d][r]  transposed Q tile
    float* sK = sm + 64*68;     // [d][c]  transposed K tile
    float* sV = sm + 2*64*68;   // [j][d]  natural V tile
    float* sP = sm + 3*64*68;   // [j][r]  transposed P tile
    const float SCALE = 0.05103103630798288f;   // 384^-0.5

    int bh = blockIdx.y;
    int b = bh / H_, h = bh % H_;
    int q0 = blockIdx.x * 64;
    const float* Q = Qh + (size_t)bh*T_*DH;
    const float* K = Kh + (size_t)bh*T_*DH;
    const float* V = Vh + (size_t)bh*T_*DH;
    int tid = threadIdx.x;
    int tx = tid & 15, ty = tid >> 4;
    int lr = tid >> 2, lc4 = (tid & 3) * 4;

    // load Q tile (transposed into [d][r])
    #pragma unroll
    for (int cg = 0; cg < 4; cg++) {
        int d = cg*16 + lc4;
        float4 q4 = make_float4(0.f,0.f,0.f,0.f);
        int gt = q0 + lr;
        if (gt < T_) q4 = *(const float4*)(Q + (size_t)gt*DH + d);
        sQ[(d+0)*68+lr] = q4.x; sQ[(d+1)*68+lr] = q4.y;
        sQ[(d+2)*68+lr] = q4.z; sQ[(d+3)*68+lr] = q4.w;
    }

    float m_i[4], l_i[4], o[4][4];
    #pragma unroll
    for (int i = 0; i < 4; i++) {
        m_i[i] = -1e30f; l_i[i] = 0.f;
        #pragma unroll
        for (int j = 0; j < 4; j++) o[i][j] = 0.f;
    }

    for (int j0 = 0; j0 < T_; j0 += 64) {
        // load K tile (transposed) and V tile (natural)
        #pragma unroll
        for (int cg = 0; cg < 4; cg++) {
            int d = cg*16 + lc4;
            int gt = j0 + lr;
            float4 k4 = make_float4(0.f,0.f,0.f,0.f);
            float4 v4 = make_float4(0.f,0.f,0.f,0.f);
            if (gt < T_) {
                k4 = *(const float4*)(K + (size_t)gt*DH + d);
                v4 = *(const float4*)(V + (size_t)gt*DH + d);
            }
            sK[(d+0)*68+lr] = k4.x; sK[(d+1)*68+lr] = k4.y;
            sK[(d+2)*68+lr] = k4.z; sK[(d+3)*68+lr] = k4.w;
            *(float4*)&sV[lr*68 + d] = v4;
        }
        __syncthreads();

        // S = Q @ K^T  (64x64, 4x4 fragment per thread)
        float s[4][4] = {};
        #pragma unroll 16
        for (int d = 0; d < 64; d++) {
            float4 a4 = *(const float4*)&sQ[d*68 + 4*ty];
            float4 b4 = *(const float4*)&sK[d*68 + 4*tx];
            float ar[4] = {a4.x, a4.y, a4.z, a4.w};
            float br[4] = {b4.x, b4.y, b4.z, b4.w};
            #pragma unroll
            for (int i = 0; i < 4; i++)
                #pragma unroll
                for (int j = 0; j < 4; j++)
                    s[i][j] = fmaf(ar[i], br[j], s[i][j]);
        }

        // online softmax (row groups = 16 lanes with same ty)
        #pragma unroll
        for (int i = 0; i < 4; i++) {
            float mx = -1e30f;
            #pragma unroll
            for (int j = 0; j < 4; j++) {
                int kidx = j0 + 4*tx + j;
                float sv = (kidx < T_) ? s[i][j]*SCALE : -1e30f;
                s[i][j] = sv;
                mx = fmaxf(mx, sv);
            }
            #pragma unroll
            for (int off = 1; off < 16; off <<= 1)
                mx = fmaxf(mx, __shfl_xor_sync(0xffffffffu, mx, off));
            float mnew  = fmaxf(m_i[i], mx);
            float alpha = __expf(m_i[i] - mnew);
            float ps = 0.f;
            #pragma unroll
            for (int j = 0; j < 4; j++) {
                float p = __expf(s[i][j] - mnew);
                s[i][j] = p; ps += p;
            }
            #pragma unroll
            for (int off = 1; off < 16; off <<= 1)
                ps += __shfl_xor_sync(0xffffffffu, ps, off);
            l_i[i] = l_i[i]*alpha + ps;
            m_i[i] = mnew;
            #pragma unroll
            for (int j = 0; j < 4; j++) o[i][j] *= alpha;
        }

        // stash P transposed: sP[key][row]
        #pragma unroll
        for (int j = 0; j < 4; j++)
            #pragma unroll
            for (int i = 0; i < 4; i++)
                sP[(4*tx + j)*68 + 4*ty + i] = s[i][j];
        __syncthreads();

        // O += P @ V
        #pragma unroll 16
        for (int j = 0; j < 64; j++) {
            float4 a4 = *(const float4*)&sP[j*68 + 4*ty];
            float4 v4 = *(const float4*)&sV[j*68 + 4*tx];
            float ar[4] = {a4.x, a4.y, a4.z, a4.w};
            float vr[4] = {v4.x, v4.y, v4.z, v4.w};
            #pragma unroll
            for (int i = 0; i < 4; i++)
                #pragma unroll
                for (int jj = 0; jj < 4; jj++)
                    o[i][jj] = fmaf(ar[i], vr[jj], o[i][jj]);
        }
        __syncthreads();
    }

    // epilogue: normalize and write (b,t,c)
    #pragma unroll
    for (int i = 0; i < 4; i++) {
        int gt = q0 + 4*ty + i;
        if (gt >= T_) continue;
        float inv = 1.0f / l_i[i];
        #pragma unroll
        for (int j = 0; j < 4; j++)
            Oa[((size_t)b*T_ + gt)*C_ + h*DH + 4*tx + j] = o[i][j]*inv;
    }
}

// ---------------- launch ----------------
extern "C" void kernel_launch(void* const* d_in, const int* in_sizes, int n_in,
                              void* d_out, int out_size)
{
    const float* x  = (const float*)d_in[0];
    // d_in[1]=h, d_in[2]=w (fixed 48x48)
    const float* kq = (const float*)d_in[3];
    const float* kk = (const float*)d_in[4];
    const float* kv = (const float*)d_in[5];
    const float* gq = (const float*)d_in[6];
    const float* bq = (const float*)d_in[7];
    const float* mq = (const float*)d_in[8];
    const float* vq = (const float*)d_in[9];
    const float* gk = (const float*)d_in[10];
    const float* bk = (const float*)d_in[11];
    const float* mk = (const float*)d_in[12];
    const float* vk = (const float*)d_in[13];
    const float* gv = (const float*)d_in[14];
    const float* bv = (const float*)d_in[15];
    const float* mv = (const float*)d_in[16];
    const float* vv = (const float*)d_in[17];
    const float* Wq = (const float*)d_in[18];
    const float* Wk = (const float*)d_in[19];
    const float* Wv = (const float*)d_in[20];
    const float* Wo = (const float*)d_in[21];
    const float* bo = (const float*)d_in[22];
    float* out = (float*)d_out;

    float *qin, *kin, *vin, *qh, *kh, *vh, *att;
    cudaGetSymbolAddress((void**)&qin, g_qin);
    cudaGetSymbolAddress((void**)&kin, g_kin);
    cudaGetSymbolAddress((void**)&vin, g_vin);
    cudaGetSymbolAddress((void**)&qh,  g_q);
    cudaGetSymbolAddress((void**)&kh,  g_k);
    cudaGetSymbolAddress((void**)&vh,  g_v);
    cudaGetSymbolAddress((void**)&att, g_att);

    prep_kernel<<<(M_*C_ + 255)/256, 256>>>(x, kq, kk, kv,
                                            gq, bq, mq, vq,
                                            gk, bk, mk, vk,
                                            gv, bv, mv, vv);

    dim3 gg((M_ + 63)/64, C_/64);
    gemm64<true ><<<gg, 256>>>(qin, Wq, nullptr, qh);
    gemm64<true ><<<gg, 256>>>(kin, Wk, nullptr, kh);
    gemm64<true ><<<gg, 256>>>(vin, Wv, nullptr, vh);

    cudaFuncSetAttribute(attn_kernel,
                         cudaFuncAttributeMaxDynamicSharedMemorySize, ATTN_SMEM);
    attn_kernel<<<dim3((T_ + 63)/64, B_*H_), 256, ATTN_SMEM>>>(qh, kh, vh, att);

    gemm64<false><<<gg, 256>>>(att, Wo, bo, out);
}

// round 3
// speedup vs baseline: 1.7393x; 1.7393x over previous
#include <cuda_runtime.h>
#include <cuda_bf16.h>
#include <math.h>
#include <stdint.h>

#define B_  4
#define T_  2305
#define C_  384
#define H_  6
#define DH  64
#define HW  48
#define M_  (B_*T_)          // 9220 rows
#define BN_EPS 1e-5f

// ---------------- device scratch (no allocations allowed) ----------------
__device__ float g_qin[M_*C_];
__device__ float g_kin[M_*C_];
__device__ float g_vin[M_*C_];
__device__ float g_q  [M_*C_];   // (b,h,t,d)
__device__ float g_k  [M_*C_];
__device__ float g_v  [M_*C_];
__device__ float g_att[M_*C_];   // (b,t,c)

// ---------------- bf16 mma.sync m16n8k16 + split helpers ----------------
__device__ __forceinline__ void mma_bf16(float c[4], const uint32_t a[4], const uint32_t b[2])
{
    asm volatile(
        "mma.sync.aligned.m16n8k16.row.col.f32.bf16.bf16.f32 "
        "{%0,%1,%2,%3}, {%4,%5,%6,%7}, {%8,%9}, {%0,%1,%2,%3};\n"
        : "+f"(c[0]), "+f"(c[1]), "+f"(c[2]), "+f"(c[3])
        : "r"(a[0]), "r"(a[1]), "r"(a[2]), "r"(a[3]), "r"(b[0]), "r"(b[1]));
}

// split (x,y) into packed bf16x2 hi and lo: hi = bf16(x), lo = bf16(x - hi)
__device__ __forceinline__ void split_pack(float x, float y, uint32_t& hi, uint32_t& lo)
{
    __nv_bfloat162 h = __floats2bfloat162_rn(x, y);           // .x low bits
    float xr = x - __bfloat162float(h.x);
    float yr = y - __bfloat162float(h.y);
    __nv_bfloat162 l = __floats2bfloat162_rn(xr, yr);
    hi = *reinterpret_cast<uint32_t*>(&h);
    lo = *reinterpret_cast<uint32_t*>(&l);
}

// ---------------- kernel 1: depthwise conv 3x3 + BN for q,k,v ----------------
__global__ void prep_kernel(const float* __restrict__ x,
    const float* __restrict__ kq, const float* __restrict__ kk,
    const float* __restrict__ kv,
    const float* __restrict__ gq, const float* __restrict__ bq,
    const float* __restrict__ mq, const float* __restrict__ vq,
    const float* __restrict__ gk, const float* __restrict__ bk,
    const float* __restrict__ mk, const float* __restrict__ vk,
    const float* __restrict__ gv, const float* __restrict__ bv,
    const float* __restrict__ mv, const float* __restrict__ vv)
{
    int idx = blockIdx.x*blockDim.x + threadIdx.x;
    if (idx >= M_*C_) return;
    int c = idx % C_;
    int t = (idx / C_) % T_;
    int b = idx / (C_*T_);
    const float* xb = x + (size_t)b*T_*C_;
    if (t == 0) {
        float v = xb[c];
        g_qin[idx] = v; g_kin[idx] = v; g_vin[idx] = v;
        return;
    }
    int p = t - 1, py = p / HW, px = p % HW;
    float aq = 0.f, ak = 0.f, av = 0.f;
    #pragma unroll
    for (int dy = 0; dy < 3; dy++) {
        int ny = py + dy - 1;
        if ((unsigned)ny >= (unsigned)HW) continue;
        #pragma unroll
        for (int dx = 0; dx < 3; dx++) {
            int nx = px + dx - 1;
            if ((unsigned)nx >= (unsigned)HW) continue;
            float xv = xb[(size_t)(1 + ny*HW + nx)*C_ + c];
            int tap = dy*3 + dx;
            aq = fmaf(xv, kq[c*9 + tap], aq);
            ak = fmaf(xv, kk[c*9 + tap], ak);
            av = fmaf(xv, kv[c*9 + tap], av);
        }
    }
    g_qin[idx] = (aq - mq[c]) * (gq[c]*rsqrtf(vq[c]+BN_EPS)) + bq[c];
    g_kin[idx] = (ak - mk[c]) * (gk[c]*rsqrtf(vk[c]+BN_EPS)) + bk[c];
    g_vin[idx] = (av - mv[c]) * (gv[c]*rsqrtf(vv[c]+BN_EPS)) + bv[c];
}

// ---------------- bf16x3 GEMM: D[m,n] = sum_k A[m,k]*W[n,k] ----------------
// BM=128, BN=64, BK=32, 256 threads (8 warps, each 16 rows x 64 cols)
template<bool HEAD_OUT>
__global__ void __launch_bounds__(256) gemm_bf3(const float* __restrict__ A,
                                                const float* __restrict__ W,
                                                const float* __restrict__ bias,
                                                float* __restrict__ D)
{
    __shared__ uint32_t sAh[128][20], sAl[128][20];   // [m][k/2] packed bf16x2
    __shared__ uint32_t sWh[64][20],  sWl[64][20];    // [n][k/2]
    int m0 = blockIdx.x*128, n0 = blockIdx.y*64;
    int tid = threadIdx.x, w = tid>>5, lane = tid&31;
    int gid = lane>>2, tig = lane&3;
    float acc[8][4] = {};
    int arow = tid>>1, ac = (tid&1)*16;
    int wrow = tid>>2, wc = (tid&3)*8;

    for (int k0 = 0; k0 < C_; k0 += 32) {
        int gm = m0 + arow;
        #pragma unroll
        for (int i = 0; i < 4; i++) {
            float4 v = (gm < M_) ? *(const float4*)(A + (size_t)gm*C_ + k0 + ac + i*4)
                                 : make_float4(0.f,0.f,0.f,0.f);
            split_pack(v.x, v.y, sAh[arow][ac/2 + 2*i    ], sAl[arow][ac/2 + 2*i    ]);
            split_pack(v.z, v.w, sAh[arow][ac/2 + 2*i + 1], sAl[arow][ac/2 + 2*i + 1]);
        }
        #pragma unroll
        for (int i = 0; i < 2; i++) {
            float4 v = *(const float4*)(W + (size_t)(n0 + wrow)*C_ + k0 + wc + i*4);
            split_pack(v.x, v.y, sWh[wrow][wc/2 + 2*i    ], sWl[wrow][wc/2 + 2*i    ]);
            split_pack(v.z, v.w, sWh[wrow][wc/2 + 2*i + 1], sWl[wrow][wc/2 + 2*i + 1]);
        }
        __syncthreads();
        #pragma unroll
        for (int ks = 0; ks < 2; ks++) {
            uint32_t ah[4], al[4];
            ah[0] = sAh[w*16+gid  ][ks*8+tig  ];
            ah[1] = sAh[w*16+gid+8][ks*8+tig  ];
            ah[2] = sAh[w*16+gid  ][ks*8+tig+4];
            ah[3] = sAh[w*16+gid+8][ks*8+tig+4];
            al[0] = sAl[w*16+gid  ][ks*8+tig  ];
            al[1] = sAl[w*16+gid+8][ks*8+tig  ];
            al[2] = sAl[w*16+gid  ][ks*8+tig+4];
            al[3] = sAl[w*16+gid+8][ks*8+tig+4];
            #pragma unroll
            for (int nt = 0; nt < 8; nt++) {
                uint32_t bh[2], bl[2];
                bh[0] = sWh[nt*8+gid][ks*8+tig  ];
                bh[1] = sWh[nt*8+gid][ks*8+tig+4];
                bl[0] = sWl[nt*8+gid][ks*8+tig  ];
                bl[1] = sWl[nt*8+gid][ks*8+tig+4];
                mma_bf16(acc[nt], ah, bh);
                mma_bf16(acc[nt], ah, bl);
                mma_bf16(acc[nt], al, bh);
            }
        }
        __syncthreads();
    }

    #pragma unroll
    for (int nt = 0; nt < 8; nt++) {
        int gn = n0 + nt*8 + 2*tig;
        #pragma unroll
        for (int half = 0; half < 2; half++) {
            int gm = m0 + w*16 + gid + half*8;
            if (gm >= M_) continue;
            float v0 = acc[nt][half*2+0], v1 = acc[nt][half*2+1];
            if (HEAD_OUT) {
                int b = gm / T_, t = gm % T_;
                int h = gn >> 6, d = gn & 63;
                float* p = &D[(((size_t)b*H_ + h)*T_ + t)*DH + d];
                p[0] = v0; p[1] = v1;
            } else {
                float* p = &D[(size_t)gm*C_ + gn];
                p[0] = v0 + bias[gn]; p[1] = v1 + bias[gn+1];
            }
        }
    }
}

// ---------------- flash attention with bf16x3 mma ----------------
// 128 threads (4 warps), 64-query CTA, 64-key tiles.
#define KSTR 36
#define ATTN_SMEM (6*64*KSTR*4)
__global__ void __launch_bounds__(128) attn_bf3(const float* __restrict__ Qh,
                                                const float* __restrict__ Kh,
                                                const float* __restrict__ Vh,
                                                float* __restrict__ Oa)
{
    extern __shared__ uint32_t su[];
    uint32_t (*sKh)[KSTR] = (uint32_t(*)[KSTR])(su);             // [key][d/2]
    uint32_t (*sKl)[KSTR] = (uint32_t(*)[KSTR])(su + 1*64*KSTR);
    uint32_t (*sVh)[KSTR] = (uint32_t(*)[KSTR])(su + 2*64*KSTR); // [d][key/2] (transposed)
    uint32_t (*sVl)[KSTR] = (uint32_t(*)[KSTR])(su + 3*64*KSTR);
    uint32_t (*sPh)[KSTR] = (uint32_t(*)[KSTR])(su + 4*64*KSTR); // [q][key/2]
    uint32_t (*sPl)[KSTR] = (uint32_t(*)[KSTR])(su + 5*64*KSTR);
    const float SCALE = 0.05103103630798288f;   // 384^-0.5

    int bh = blockIdx.y;
    int b = bh / H_, h = bh % H_;
    int q0 = blockIdx.x * 64;
    const float* Q = Qh + (size_t)bh*T_*DH;
    const float* K = Kh + (size_t)bh*T_*DH;
    const float* V = Vh + (size_t)bh*T_*DH;
    int tid = threadIdx.x, w = tid>>5, lane = tid&31;
    int gid = lane>>2, tig = lane&3;
    int r0 = q0 + w*16 + gid, r1 = r0 + 8;
    int pr0 = w*16 + gid, pr1 = pr0 + 8;

    // preload Q as split A-fragments (registers, once per CTA)
    uint32_t qfh[4][4], qfl[4][4];
    #pragma unroll
    for (int ks = 0; ks < 4; ks++) {
        int c0 = ks*16 + 2*tig;
        float2 x0 = (r0 < T_) ? *(const float2*)(Q + (size_t)r0*DH + c0    ) : make_float2(0.f,0.f);
        float2 x1 = (r1 < T_) ? *(const float2*)(Q + (size_t)r1*DH + c0    ) : make_float2(0.f,0.f);
        float2 x2 = (r0 < T_) ? *(const float2*)(Q + (size_t)r0*DH + c0 + 8) : make_float2(0.f,0.f);
        float2 x3 = (r1 < T_) ? *(const float2*)(Q + (size_t)r1*DH + c0 + 8) : make_float2(0.f,0.f);
        split_pack(x0.x, x0.y, qfh[ks][0], qfl[ks][0]);
        split_pack(x1.x, x1.y, qfh[ks][1], qfl[ks][1]);
        split_pack(x2.x, x2.y, qfh[ks][2], qfl[ks][2]);
        split_pack(x3.x, x3.y, qfh[ks][3], qfl[ks][3]);
    }

    float m0v = -1e30f, m1v = -1e30f, l0 = 0.f, l1 = 0.f;
    float o[8][4] = {};

    int krow = tid>>1, kc = (tid&1)*32;       // K loader
    int kp = tid&31, dblk = (tid>>5)*16;      // V loader (transpose)

    for (int j0 = 0; j0 < T_; j0 += 64) {
        __syncthreads();
        {   // K tile: [key][d/2] packed
            int gt = j0 + krow;
            bool valid = gt < T_;
            #pragma unroll
            for (int i = 0; i < 8; i++) {
                float4 v = valid ? *(const float4*)(K + (size_t)gt*DH + kc + i*4)
                                 : make_float4(0.f,0.f,0.f,0.f);
                split_pack(v.x, v.y, sKh[krow][kc/2 + 2*i    ], sKl[krow][kc/2 + 2*i    ]);
                split_pack(v.z, v.w, sKh[krow][kc/2 + 2*i + 1], sKl[krow][kc/2 + 2*i + 1]);
            }
            // V tile transposed: [d][key/2], pair = (key even, key odd)
            int k0g = j0 + 2*kp, k1g = k0g + 1;
            bool v0ok = k0g < T_, v1ok = k1g < T_;
            #pragma unroll
            for (int i = 0; i < 4; i++) {
                float4 va = v0ok ? *(const float4*)(V + (size_t)k0g*DH + dblk + i*4)
                                 : make_float4(0.f,0.f,0.f,0.f);
                float4 vb = v1ok ? *(const float4*)(V + (size_t)k1g*DH + dblk + i*4)
                                 : make_float4(0.f,0.f,0.f,0.f);
                split_pack(va.x, vb.x, sVh[dblk+i*4  ][kp], sVl[dblk+i*4  ][kp]);
                split_pack(va.y, vb.y, sVh[dblk+i*4+1][kp], sVl[dblk+i*4+1][kp]);
                split_pack(va.z, vb.z, sVh[dblk+i*4+2][kp], sVl[dblk+i*4+2][kp]);
                split_pack(va.w, vb.w, sVh[dblk+i*4+3][kp], sVl[dblk+i*4+3][kp]);
            }
        }
        __syncthreads();

        // S = Q @ K^T (bf16x3)
        float s[8][4] = {};
        #pragma unroll
        for (int ks = 0; ks < 4; ks++) {
            #pragma unroll
            for (int nt = 0; nt < 8; nt++) {
                uint32_t bh2[2], bl2[2];
                bh2[0] = sKh[nt*8+gid][ks*8+tig  ];
                bh2[1] = sKh[nt*8+gid][ks*8+tig+4];
                bl2[0] = sKl[nt*8+gid][ks*8+tig  ];
                bl2[1] = sKl[nt*8+gid][ks*8+tig+4];
                mma_bf16(s[nt], qfh[ks], bh2);
                mma_bf16(s[nt], qfh[ks], bl2);
                mma_bf16(s[nt], qfl[ks], bh2);
            }
        }

        // online softmax
        float mx0 = -1e30f, mx1 = -1e30f;
        #pragma unroll
        for (int nt = 0; nt < 8; nt++) {
            int cb = j0 + nt*8 + 2*tig;
            bool c0ok = cb < T_, c1ok = (cb+1) < T_;
            s[nt][0] = c0ok ? s[nt][0]*SCALE : -1e30f;
            s[nt][1] = c1ok ? s[nt][1]*SCALE : -1e30f;
            s[nt][2] = c0ok ? s[nt][2]*SCALE : -1e30f;
            s[nt][3] = c1ok ? s[nt][3]*SCALE : -1e30f;
            mx0 = fmaxf(mx0, fmaxf(s[nt][0], s[nt][1]));
            mx1 = fmaxf(mx1, fmaxf(s[nt][2], s[nt][3]));
        }
        mx0 = fmaxf(mx0, __shfl_xor_sync(0xffffffffu, mx0, 1));
        mx0 = fmaxf(mx0, __shfl_xor_sync(0xffffffffu, mx0, 2));
        mx1 = fmaxf(mx1, __shfl_xor_sync(0xffffffffu, mx1, 1));
        mx1 = fmaxf(mx1, __shfl_xor_sync(0xffffffffu, mx1, 2));

        float m0n = fmaxf(m0v, mx0), m1n = fmaxf(m1v, mx1);
        float a0 = __expf(m0v - m0n), a1 = __expf(m1v - m1n);
        float ps0 = 0.f, ps1 = 0.f;
        #pragma unroll
        for (int nt = 0; nt < 8; nt++) {
            s[nt][0] = __expf(s[nt][0] - m0n);
            s[nt][1] = __expf(s[nt][1] - m0n);
            s[nt][2] = __expf(s[nt][2] - m1n);
            s[nt][3] = __expf(s[nt][3] - m1n);
            ps0 += s[nt][0] + s[nt][1];
            ps1 += s[nt][2] + s[nt][3];
        }
        ps0 += __shfl_xor_sync(0xffffffffu, ps0, 1);
        ps0 += __shfl_xor_sync(0xffffffffu, ps0, 2);
        ps1 += __shfl_xor_sync(0xffffffffu, ps1, 1);
        ps1 += __shfl_xor_sync(0xffffffffu, ps1, 2);
        l0 = l0*a0 + ps0;  m0v = m0n;
        l1 = l1*a1 + ps1;  m1v = m1n;
        #pragma unroll
        for (int nt = 0; nt < 8; nt++) {
            o[nt][0] *= a0; o[nt][1] *= a0;
            o[nt][2] *= a1; o[nt][3] *= a1;
        }

        // stash P split (warp-private rows)
        #pragma unroll
        for (int nt = 0; nt < 8; nt++) {
            split_pack(s[nt][0], s[nt][1], sPh[pr0][nt*4+tig], sPl[pr0][nt*4+tig]);
            split_pack(s[nt][2], s[nt][3], sPh[pr1][nt*4+tig], sPl[pr1][nt*4+tig]);
        }
        __syncwarp();

        // O += P @ V (bf16x3)
        #pragma unroll
        for (int ks = 0; ks < 4; ks++) {
            uint32_t ah[4], al[4];
            ah[0] = sPh[pr0][ks*8+tig  ];
            ah[1] = sPh[pr1][ks*8+tig  ];
            ah[2] = sPh[pr0][ks*8+tig+4];
            ah[3] = sPh[pr1][ks*8+tig+4];
            al[0] = sPl[pr0][ks*8+tig  ];
            al[1] = sPl[pr1][ks*8+tig  ];
            al[2] = sPl[pr0][ks*8+tig+4];
            al[3] = sPl[pr1][ks*8+tig+4];
            #pragma unroll
            for (int nt = 0; nt < 8; nt++) {
                uint32_t bh2[2], bl2[2];
                bh2[0] = sVh[nt*8+gid][ks*8+tig  ];
                bh2[1] = sVh[nt*8+gid][ks*8+tig+4];
                bl2[0] = sVl[nt*8+gid][ks*8+tig  ];
                bl2[1] = sVl[nt*8+gid][ks*8+tig+4];
                mma_bf16(o[nt], ah, bh2);
                mma_bf16(o[nt], ah, bl2);
                mma_bf16(o[nt], al, bh2);
            }
        }
    }

    // epilogue: normalize, write (b,t,c)
    float inv0 = 1.0f / l0, inv1 = 1.0f / l1;
    #pragma unroll
    for (int nt = 0; nt < 8; nt++) {
        int d = nt*8 + 2*tig;
        if (r0 < T_)
            *(float2*)&Oa[((size_t)b*T_ + r0)*C_ + h*DH + d] =
                make_float2(o[nt][0]*inv0, o[nt][1]*inv0);
        if (r1 < T_)
            *(float2*)&Oa[((size_t)b*T_ + r1)*C_ + h*DH + d] =
                make_float2(o[nt][2]*inv1, o[nt][3]*inv1);
    }
}

// ---------------- launch ----------------
extern "C" void kernel_launch(void* const* d_in, const int* in_sizes, int n_in,
                              void* d_out, int out_size)
{
    const float* x  = (const float*)d_in[0];
    const float* kq = (const float*)d_in[3];
    const float* kk = (const float*)d_in[4];
    const float* kv = (const float*)d_in[5];
    const float* gq = (const float*)d_in[6];
    const float* bq = (const float*)d_in[7];
    const float* mq = (const float*)d_in[8];
    const float* vq = (const float*)d_in[9];
    const float* gk = (const float*)d_in[10];
    const float* bk = (const float*)d_in[11];
    const float* mk = (const float*)d_in[12];
    const float* vk = (const float*)d_in[13];
    const float* gv = (const float*)d_in[14];
    const float* bv = (const float*)d_in[15];
    const float* mv = (const float*)d_in[16];
    const float* vv = (const float*)d_in[17];
    const float* Wq = (const float*)d_in[18];
    const float* Wk = (const float*)d_in[19];
    const float* Wv = (const float*)d_in[20];
    const float* Wo = (const float*)d_in[21];
    const float* bo = (const float*)d_in[22];
    float* out = (float*)d_out;

    float *qin, *kin, *vin, *qh, *kh, *vh, *att;
    cudaGetSymbolAddress((void**)&qin, g_qin);
    cudaGetSymbolAddress((void**)&kin, g_kin);
    cudaGetSymbolAddress((void**)&vin, g_vin);
    cudaGetSymbolAddress((void**)&qh,  g_q);
    cudaGetSymbolAddress((void**)&kh,  g_k);
    cudaGetSymbolAddress((void**)&vh,  g_v);
    cudaGetSymbolAddress((void**)&att, g_att);

    prep_kernel<<<(M_*C_ + 255)/256, 256>>>(x, kq, kk, kv,
                                            gq, bq, mq, vq,
                                            gk, bk, mk, vk,
                                            gv, bv, mv, vv);

    dim3 gg((M_ + 127)/128, C_/64);
    gemm_bf3<true ><<<gg, 256>>>(qin, Wq, nullptr, qh);
    gemm_bf3<true ><<<gg, 256>>>(kin, Wk, nullptr, kh);
    gemm_bf3<true ><<<gg, 256>>>(vin, Wv, nullptr, vh);

    cudaFuncSetAttribute(attn_bf3,
                         cudaFuncAttributeMaxDynamicSharedMemorySize, ATTN_SMEM);
    attn_bf3<<<dim3((T_ + 63)/64, B_*H_), 128, ATTN_SMEM>>>(qh, kh, vh, att);

    gemm_bf3<false><<<gg, 256>>>(att, Wo, bo, out);
}

// round 6
// speedup vs baseline: 2.4230x; 1.3931x over previous
#include <cuda_runtime.h>
#include <cuda_bf16.h>
#include <math.h>
#include <stdint.h>

#define B_  4
#define T_  2305
#define C_  384
#define H_  6
#define BH_ (B_*H_)          // 24
#define DH  64
#define HW  48
#define M_  (B_*T_)          // 9220 rows
#define BN_EPS 1e-5f
#define NKT 37               // key tiles of 64
#define KT  (NKT*64)         // 2368 padded keys
#define TP  (KT/2)           // 1184 padded key-pairs

// ---------------- device scratch (256B-aligned) ----------------
__device__ __align__(256) float g_qin[M_*C_];
__device__ __align__(256) float g_kin[M_*C_];
__device__ __align__(256) float g_vin[M_*C_];
__device__ __align__(256) float g_q  [M_*C_];            // (b,h,t,d) fp32
__device__ __align__(256) float g_v  [M_*C_];            // (b,h,t,d) fp32
__device__ __align__(256) uint32_t g_khi[BH_*KT*(DH/2)]; // (b,h)[t][d/2] bf16x2, zero-padded
__device__ __align__(256) uint32_t g_klo[BH_*KT*(DH/2)];
__device__ __align__(256) uint32_t g_vthi[BH_*DH*TP];    // (b,h)[d][tpair] bf16x2, zero-padded
__device__ __align__(256) uint32_t g_vtlo[BH_*DH*TP];
__device__ __align__(256) float g_att[M_*C_];            // (b,t,c)

// ---------------- bf16 mma m16n8k16 + split helpers ----------------
__device__ __forceinline__ void mma_bf16(float c[4], const uint32_t a[4], const uint32_t b[2])
{
    asm volatile(
        "mma.sync.aligned.m16n8k16.row.col.f32.bf16.bf16.f32 "
        "{%0,%1,%2,%3}, {%4,%5,%6,%7}, {%8,%9}, {%0,%1,%2,%3};\n"
        : "+f"(c[0]), "+f"(c[1]), "+f"(c[2]), "+f"(c[3])
        : "r"(a[0]), "r"(a[1]), "r"(a[2]), "r"(a[3]), "r"(b[0]), "r"(b[1]));
}

__device__ __forceinline__ void split_pack(float x, float y, uint32_t& hi, uint32_t& lo)
{
    __nv_bfloat162 h = __floats2bfloat162_rn(x, y);
    float xr = x - __bfloat162float(h.x);
    float yr = y - __bfloat162float(h.y);
    __nv_bfloat162 l = __floats2bfloat162_rn(xr, yr);
    hi = *reinterpret_cast<uint32_t*>(&h);
    lo = *reinterpret_cast<uint32_t*>(&l);
}

// ---------------- kernel 1: depthwise conv 3x3 + BN ----------------
__global__ void prep_kernel(const float* __restrict__ x,
    const float* __restrict__ kq, const float* __restrict__ kk,
    const float* __restrict__ kv,
    const float* __restrict__ gq, const float* __restrict__ bq,
    const float* __restrict__ mq, const float* __restrict__ vq,
    const float* __restrict__ gk, const float* __restrict__ bk,
    const float* __restrict__ mk, const float* __restrict__ vk,
    const float* __restrict__ gv, const float* __restrict__ bv,
    const float* __restrict__ mv, const float* __restrict__ vv)
{
    int idx = blockIdx.x*blockDim.x + threadIdx.x;
    if (idx >= M_*C_) return;
    int c = idx % C_;
    int t = (idx / C_) % T_;
    int b = idx / (C_*T_);
    const float* xb = x + (size_t)b*T_*C_;
    if (t == 0) {
        float v = xb[c];
        g_qin[idx] = v; g_kin[idx] = v; g_vin[idx] = v;
        return;
    }
    int p = t - 1, py = p / HW, px = p % HW;
    float aq = 0.f, ak = 0.f, av = 0.f;
    #pragma unroll
    for (int dy = 0; dy < 3; dy++) {
        int ny = py + dy - 1;
        if ((unsigned)ny >= (unsigned)HW) continue;
        #pragma unroll
        for (int dx = 0; dx < 3; dx++) {
            int nx = px + dx - 1;
            if ((unsigned)nx >= (unsigned)HW) continue;
            float xv = xb[(size_t)(1 + ny*HW + nx)*C_ + c];
            int tap = dy*3 + dx;
            aq = fmaf(xv, kq[c*9 + tap], aq);
            ak = fmaf(xv, kk[c*9 + tap], ak);
            av = fmaf(xv, kv[c*9 + tap], av);
        }
    }
    g_qin[idx] = (aq - mq[c]) * (gq[c]*rsqrtf(vq[c]+BN_EPS)) + bq[c];
    g_kin[idx] = (ak - mk[c]) * (gk[c]*rsqrtf(vk[c]+BN_EPS)) + bk[c];
    g_vin[idx] = (av - mv[c]) * (gv[c]*rsqrtf(vv[c]+BN_EPS)) + bv[c];
}

// ---------------- fused QKV GEMM (pipelined, bf16x3) ----------------
__global__ void __launch_bounds__(256) gemm_qkv(
    const float* __restrict__ Aq, const float* __restrict__ Ak, const float* __restrict__ Av,
    const float* __restrict__ Wq, const float* __restrict__ Wk, const float* __restrict__ Wv,
    float* __restrict__ Dq, float* __restrict__ Dv,
    uint32_t* __restrict__ Khi, uint32_t* __restrict__ Klo)
{
    __shared__ uint32_t sAh[128][20], sAl[128][20];
    __shared__ uint32_t sWh[64][20],  sWl[64][20];
    int z = blockIdx.z;
    const float* A = (z==0) ? Aq : (z==1) ? Ak : Av;
    const float* W = (z==0) ? Wq : (z==1) ? Wk : Wv;
    int m0 = blockIdx.x*128, n0 = blockIdx.y*64;
    int tid = threadIdx.x, w = tid>>5, lane = tid&31;
    int gid = lane>>2, tig = lane&3;
    float acc[8][4] = {};
    int arow = tid>>1, ac = (tid&1)*16;
    int wrow = tid>>2, wc = (tid&3)*8;
    int gm = m0 + arow;

    float4 ra[4], rw[2];
    #pragma unroll
    for (int i = 0; i < 4; i++)
        ra[i] = (gm < M_) ? *(const float4*)(A + (size_t)gm*C_ + ac + i*4)
                          : make_float4(0.f,0.f,0.f,0.f);
    #pragma unroll
    for (int i = 0; i < 2; i++)
        rw[i] = *(const float4*)(W + (size_t)(n0 + wrow)*C_ + wc + i*4);

    for (int k0 = 0; k0 < C_; k0 += 32) {
        #pragma unroll
        for (int i = 0; i < 4; i++) {
            split_pack(ra[i].x, ra[i].y, sAh[arow][ac/2 + 2*i    ], sAl[arow][ac/2 + 2*i    ]);
            split_pack(ra[i].z, ra[i].w, sAh[arow][ac/2 + 2*i + 1], sAl[arow][ac/2 + 2*i + 1]);
        }
        #pragma unroll
        for (int i = 0; i < 2; i++) {
            split_pack(rw[i].x, rw[i].y, sWh[wrow][wc/2 + 2*i    ], sWl[wrow][wc/2 + 2*i    ]);
            split_pack(rw[i].z, rw[i].w, sWh[wrow][wc/2 + 2*i + 1], sWl[wrow][wc/2 + 2*i + 1]);
        }
        __syncthreads();
        if (k0 + 32 < C_) {
            #pragma unroll
            for (int i = 0; i < 4; i++)
                ra[i] = (gm < M_) ? *(const float4*)(A + (size_t)gm*C_ + k0+32 + ac + i*4)
                                  : make_float4(0.f,0.f,0.f,0.f);
            #pragma unroll
            for (int i = 0; i < 2; i++)
                rw[i] = *(const float4*)(W + (size_t)(n0 + wrow)*C_ + k0+32 + wc + i*4);
        }
        #pragma unroll
        for (int ks = 0; ks < 2; ks++) {
            uint32_t ah[4], al[4];
            ah[0] = sAh[w*16+gid  ][ks*8+tig  ];
            ah[1] = sAh[w*16+gid+8][ks*8+tig  ];
            ah[2] = sAh[w*16+gid  ][ks*8+tig+4];
            ah[3] = sAh[w*16+gid+8][ks*8+tig+4];
            al[0] = sAl[w*16+gid  ][ks*8+tig  ];
            al[1] = sAl[w*16+gid+8][ks*8+tig  ];
            al[2] = sAl[w*16+gid  ][ks*8+tig+4];
            al[3] = sAl[w*16+gid+8][ks*8+tig+4];
            #pragma unroll
            for (int nt = 0; nt < 8; nt++) {
                uint32_t bh[2], bl[2];
                bh[0] = sWh[nt*8+gid][ks*8+tig  ];
                bh[1] = sWh[nt*8+gid][ks*8+tig+4];
                bl[0] = sWl[nt*8+gid][ks*8+tig  ];
                bl[1] = sWl[nt*8+gid][ks*8+tig+4];
                mma_bf16(acc[nt], ah, bh);
                mma_bf16(acc[nt], ah, bl);
                mma_bf16(acc[nt], al, bh);
            }
        }
        __syncthreads();
    }

    #pragma unroll
    for (int nt = 0; nt < 8; nt++) {
        int gn = n0 + nt*8 + 2*tig;
        #pragma unroll
        for (int half = 0; half < 2; half++) {
            int gmo = m0 + w*16 + gid + half*8;
            if (gmo >= M_) continue;
            float v0 = acc[nt][half*2+0], v1 = acc[nt][half*2+1];
            int b = gmo / T_, t = gmo % T_;
            int h = gn >> 6, d = gn & 63;
            if (z == 1) {
                uint32_t hi, lo;
                split_pack(v0, v1, hi, lo);
                size_t p = ((size_t)(b*H_ + h)*KT + t)*(DH/2) + (d>>1);
                Khi[p] = hi; Klo[p] = lo;
            } else {
                float* D = (z==0) ? Dq : Dv;
                float* p = &D[(((size_t)b*H_ + h)*T_ + t)*DH + d];
                p[0] = v0; p[1] = v1;
            }
        }
    }
}

// ---------------- output GEMM (pipelined, bf16x3, bias) ----------------
__global__ void __launch_bounds__(256) gemm_o(
    const float* __restrict__ A, const float* __restrict__ W,
    const float* __restrict__ bias, float* __restrict__ D)
{
    __shared__ uint32_t sAh[128][20], sAl[128][20];
    __shared__ uint32_t sWh[64][20],  sWl[64][20];
    int m0 = blockIdx.x*128, n0 = blockIdx.y*64;
    int tid = threadIdx.x, w = tid>>5, lane = tid&31;
    int gid = lane>>2, tig = lane&3;
    float acc[8][4] = {};
    int arow = tid>>1, ac = (tid&1)*16;
    int wrow = tid>>2, wc = (tid&3)*8;
    int gm = m0 + arow;

    float4 ra[4], rw[2];
    #pragma unroll
    for (int i = 0; i < 4; i++)
        ra[i] = (gm < M_) ? *(const float4*)(A + (size_t)gm*C_ + ac + i*4)
                          : make_float4(0.f,0.f,0.f,0.f);
    #pragma unroll
    for (int i = 0; i < 2; i++)
        rw[i] = *(const float4*)(W + (size_t)(n0 + wrow)*C_ + wc + i*4);

    for (int k0 = 0; k0 < C_; k0 += 32) {
        #pragma unroll
        for (int i = 0; i < 4; i++) {
            split_pack(ra[i].x, ra[i].y, sAh[arow][ac/2 + 2*i    ], sAl[arow][ac/2 + 2*i    ]);
            split_pack(ra[i].z, ra[i].w, sAh[arow][ac/2 + 2*i + 1], sAl[arow][ac/2 + 2*i + 1]);
        }
        #pragma unroll
        for (int i = 0; i < 2; i++) {
            split_pack(rw[i].x, rw[i].y, sWh[wrow][wc/2 + 2*i    ], sWl[wrow][wc/2 + 2*i    ]);
            split_pack(rw[i].z, rw[i].w, sWh[wrow][wc/2 + 2*i + 1], sWl[wrow][wc/2 + 2*i + 1]);
        }
        __syncthreads();
        if (k0 + 32 < C_) {
            #pragma unroll
            for (int i = 0; i < 4; i++)
                ra[i] = (gm < M_) ? *(const float4*)(A + (size_t)gm*C_ + k0+32 + ac + i*4)
                                  : make_float4(0.f,0.f,0.f,0.f);
            #pragma unroll
            for (int i = 0; i < 2; i++)
                rw[i] = *(const float4*)(W + (size_t)(n0 + wrow)*C_ + k0+32 + wc + i*4);
        }
        #pragma unroll
        for (int ks = 0; ks < 2; ks++) {
            uint32_t ah[4], al[4];
            ah[0] = sAh[w*16+gid  ][ks*8+tig  ];
            ah[1] = sAh[w*16+gid+8][ks*8+tig  ];
            ah[2] = sAh[w*16+gid  ][ks*8+tig+4];
            ah[3] = sAh[w*16+gid+8][ks*8+tig+4];
            al[0] = sAl[w*16+gid  ][ks*8+tig  ];
            al[1] = sAl[w*16+gid+8][ks*8+tig  ];
            al[2] = sAl[w*16+gid  ][ks*8+tig+4];
            al[3] = sAl[w*16+gid+8][ks*8+tig+4];
            #pragma unroll
            for (int nt = 0; nt < 8; nt++) {
                uint32_t bh[2], bl[2];
                bh[0] = sWh[nt*8+gid][ks*8+tig  ];
                bh[1] = sWh[nt*8+gid][ks*8+tig+4];
                bl[0] = sWl[nt*8+gid][ks*8+tig  ];
                bl[1] = sWl[nt*8+gid][ks*8+tig+4];
                mma_bf16(acc[nt], ah, bh);
                mma_bf16(acc[nt], ah, bl);
                mma_bf16(acc[nt], al, bh);
            }
        }
        __syncthreads();
    }

    #pragma unroll
    for (int nt = 0; nt < 8; nt++) {
        int gn = n0 + nt*8 + 2*tig;
        #pragma unroll
        for (int half = 0; half < 2; half++) {
            int gmo = m0 + w*16 + gid + half*8;
            if (gmo >= M_) continue;
            float* p = &D[(size_t)gmo*C_ + gn];
            p[0] = acc[nt][half*2+0] + bias[gn];
            p[1] = acc[nt][half*2+1] + bias[gn+1];
        }
    }
}

// ---------------- V transpose + split pack ----------------
// NOTE: tile stride must be a multiple of 4 floats so float4 smem stores stay
// 16B-aligned (stride 33 was the round-4/5 "misaligned address" bug).
__global__ void __launch_bounds__(256) vpack(const float* __restrict__ V,
                                             uint32_t* __restrict__ Vthi,
                                             uint32_t* __restrict__ Vtlo)
{
    __shared__ float tile[64][36];
    int bh = blockIdx.z, db = blockIdx.y*32, tp0 = blockIdx.x*32;
    int t0 = tp0*2;
    int tid = threadIdx.x;
    {
        int tr = tid >> 2;
        int dc = (tid & 3) * 8;
        int gt = t0 + tr;
        if (gt < T_) {
            const float* src = V + ((size_t)bh*T_ + gt)*DH + db + dc;
            float4 v0 = *(const float4*)src;
            float4 v1 = *(const float4*)(src + 4);
            *(float4*)&tile[tr][dc]   = v0;
            *(float4*)&tile[tr][dc+4] = v1;
        } else {
            float4 z = make_float4(0.f,0.f,0.f,0.f);
            *(float4*)&tile[tr][dc]   = z;
            *(float4*)&tile[tr][dc+4] = z;
        }
    }
    __syncthreads();
    {
        int d = tid >> 3;
        int tpc = (tid & 7) * 4;
        #pragma unroll
        for (int i = 0; i < 4; i++) {
            int tp = tpc + i;
            uint32_t hi, lo;
            split_pack(tile[2*tp][d], tile[2*tp+1][d], hi, lo);
            size_t p = ((size_t)bh*DH + db + d)*TP + tp0 + tp;
            Vthi[p] = hi; Vtlo[p] = lo;
        }
    }
}

// ---------------- flash attention: register P, cp.async double-buffer ----------------
#define QB 128
#define BUFU 9216                 // u32 per buffer (4 arrays * 64 * 36)
#define ATTN_SMEM (2*BUFU*4)
__global__ void __launch_bounds__(256,2) attn_tc2(
    const float* __restrict__ Qh,
    const uint32_t* __restrict__ Khi, const uint32_t* __restrict__ Klo,
    const uint32_t* __restrict__ Vthi, const uint32_t* __restrict__ Vtlo,
    float* __restrict__ Oa)
{
    extern __shared__ uint32_t su[];
    const float SCALE = 0.05103103630798288f;   // 384^-0.5
    int bh = blockIdx.y, b = bh / H_, h = bh % H_;
    int q0 = blockIdx.x * QB;
    int tid = threadIdx.x, w = tid>>5, lane = tid&31;
    int gid = lane>>2, tig = lane&3;
    int r0 = q0 + w*16 + gid, r1 = r0 + 8;
    const float* Q = Qh + (size_t)bh*T_*DH;

    uint32_t qfh[4][4], qfl[4][4];
    #pragma unroll
    for (int ks = 0; ks < 4; ks++) {
        int c0 = ks*16 + 2*tig;
        float2 x0 = (r0 < T_) ? *(const float2*)(Q + (size_t)r0*DH + c0    ) : make_float2(0.f,0.f);
        float2 x1 = (r1 < T_) ? *(const float2*)(Q + (size_t)r1*DH + c0    ) : make_float2(0.f,0.f);
        float2 x2 = (r0 < T_) ? *(const float2*)(Q + (size_t)r0*DH + c0 + 8) : make_float2(0.f,0.f);
        float2 x3 = (r1 < T_) ? *(const float2*)(Q + (size_t)r1*DH + c0 + 8) : make_float2(0.f,0.f);
        split_pack(x0.x*SCALE, x0.y*SCALE, qfh[ks][0], qfl[ks][0]);
        split_pack(x1.x*SCALE, x1.y*SCALE, qfh[ks][1], qfl[ks][1]);
        split_pack(x2.x*SCALE, x2.y*SCALE, qfh[ks][2], qfl[ks][2]);
        split_pack(x3.x*SCALE, x3.y*SCALE, qfh[ks][3], qfl[ks][3]);
    }

    uint32_t sb = (uint32_t)__cvta_generic_to_shared(su);
    const uint32_t* gbase[4] = {
        Khi  + (size_t)bh*KT*(DH/2),
        Klo  + (size_t)bh*KT*(DH/2),
        Vthi + (size_t)bh*DH*TP,
        Vtlo + (size_t)bh*DH*TP };

    auto issue_tile = [&](int j0, int buf) {
        int tp0 = j0 >> 1;
        #pragma unroll
        for (int i = 0; i < 8; i++) {
            int idx = i*256 + tid;
            int arr = idx >> 9;
            int rem = idx & 511;
            int row = rem >> 3, c = (rem & 7) * 4;
            const uint32_t* g = (arr < 2)
                ? gbase[arr] + ((size_t)(j0 + row))*(DH/2) + c
                : gbase[arr] + ((size_t)row)*TP + tp0 + c;
            uint32_t dst = sb + (buf*BUFU + arr*2304 + row*36 + c)*4;
            asm volatile("cp.async.cg.shared.global [%0], [%1], 16;\n" :: "r"(dst), "l"(g));
        }
        asm volatile("cp.async.commit_group;\n");
    };

    float m0v = -1e30f, m1v = -1e30f, l0 = 0.f, l1 = 0.f;
    float o[8][4] = {};

    issue_tile(0, 0);

    for (int it = 0; it < NKT; it++) {
        asm volatile("cp.async.wait_group 0;\n" ::: "memory");
        __syncthreads();
        if (it + 1 < NKT) issue_tile((it+1)*64, (it+1)&1);

        const uint32_t* bKh = su + (it&1)*BUFU + 0*2304;
        const uint32_t* bKl = su + (it&1)*BUFU + 1*2304;
        const uint32_t* bVh = su + (it&1)*BUFU + 2*2304;
        const uint32_t* bVl = su + (it&1)*BUFU + 3*2304;
        int j0 = it*64;

        float s[8][4] = {};
        #pragma unroll
        for (int ks = 0; ks < 4; ks++) {
            #pragma unroll
            for (int nt = 0; nt < 8; nt++) {
                uint32_t bh2[2], bl2[2];
                bh2[0] = bKh[(nt*8+gid)*36 + ks*8+tig  ];
                bh2[1] = bKh[(nt*8+gid)*36 + ks*8+tig+4];
                bl2[0] = bKl[(nt*8+gid)*36 + ks*8+tig  ];
                bl2[1] = bKl[(nt*8+gid)*36 + ks*8+tig+4];
                mma_bf16(s[nt], qfh[ks], bh2);
                mma_bf16(s[nt], qfh[ks], bl2);
                mma_bf16(s[nt], qfl[ks], bh2);
            }
        }

        float mx0 = -1e30f, mx1 = -1e30f;
        #pragma unroll
        for (int nt = 0; nt < 8; nt++) {
            int cb = j0 + nt*8 + 2*tig;
            bool c0ok = cb < T_, c1ok = (cb+1) < T_;
            s[nt][0] = c0ok ? s[nt][0] : -1e30f;
            s[nt][1] = c1ok ? s[nt][1] : -1e30f;
            s[nt][2] = c0ok ? s[nt][2] : -1e30f;
            s[nt][3] = c1ok ? s[nt][3] : -1e30f;
            mx0 = fmaxf(mx0, fmaxf(s[nt][0], s[nt][1]));
            mx1 = fmaxf(mx1, fmaxf(s[nt][2], s[nt][3]));
        }
        mx0 = fmaxf(mx0, __shfl_xor_sync(0xffffffffu, mx0, 1));
        mx0 = fmaxf(mx0, __shfl_xor_sync(0xffffffffu, mx0, 2));
        mx1 = fmaxf(mx1, __shfl_xor_sync(0xffffffffu, mx1, 1));
        mx1 = fmaxf(mx1, __shfl_xor_sync(0xffffffffu, mx1, 2));

        float m0n = fmaxf(m0v, mx0), m1n = fmaxf(m1v, mx1);
        float a0 = __expf(m0v - m0n), a1 = __expf(m1v - m1n);
        float ps0 = 0.f, ps1 = 0.f;
        #pragma unroll
        for (int nt = 0; nt < 8; nt++) {
            s[nt][0] = __expf(s[nt][0] - m0n);
            s[nt][1] = __expf(s[nt][1] - m0n);
            s[nt][2] = __expf(s[nt][2] - m1n);
            s[nt][3] = __expf(s[nt][3] - m1n);
            ps0 += s[nt][0] + s[nt][1];
            ps1 += s[nt][2] + s[nt][3];
        }
        ps0 += __shfl_xor_sync(0xffffffffu, ps0, 1);
        ps0 += __shfl_xor_sync(0xffffffffu, ps0, 2);
        ps1 += __shfl_xor_sync(0xffffffffu, ps1, 1);
        ps1 += __shfl_xor_sync(0xffffffffu, ps1, 2);
        l0 = l0*a0 + ps0;  m0v = m0n;
        l1 = l1*a1 + ps1;  m1v = m1n;
        #pragma unroll
        for (int nt = 0; nt < 8; nt++) {
            o[nt][0] *= a0; o[nt][1] *= a0;
            o[nt][2] *= a1; o[nt][3] *= a1;
        }

        #pragma unroll
        for (int ks = 0; ks < 4; ks++) {
            uint32_t ah[4], al[4];
            split_pack(s[2*ks  ][0], s[2*ks  ][1], ah[0], al[0]);
            split_pack(s[2*ks  ][2], s[2*ks  ][3], ah[1], al[1]);
            split_pack(s[2*ks+1][0], s[2*ks+1][1], ah[2], al[2]);
            split_pack(s[2*ks+1][2], s[2*ks+1][3], ah[3], al[3]);
            #pragma unroll
            for (int nt = 0; nt < 8; nt++) {
                uint32_t bh2[2], bl2[2];
                bh2[0] = bVh[(nt*8+gid)*36 + ks*8+tig  ];
                bh2[1] = bVh[(nt*8+gid)*36 + ks*8+tig+4];
                bl2[0] = bVl[(nt*8+gid)*36 + ks*8+tig  ];
                bl2[1] = bVl[(nt*8+gid)*36 + ks*8+tig+4];
                mma_bf16(o[nt], ah, bh2);
                mma_bf16(o[nt], ah, bl2);
                mma_bf16(o[nt], al, bh2);
            }
        }
    }

    float inv0 = 1.0f / l0, inv1 = 1.0f / l1;
    #pragma unroll
    for (int nt = 0; nt < 8; nt++) {
        int d = nt*8 + 2*tig;
        if (r0 < T_)
            *(float2*)&Oa[((size_t)b*T_ + r0)*C_ + h*DH + d] =
                make_float2(o[nt][0]*inv0, o[nt][1]*inv0);
        if (r1 < T_)
            *(float2*)&Oa[((size_t)b*T_ + r1)*C_ + h*DH + d] =
                make_float2(o[nt][2]*inv1, o[nt][3]*inv1);
    }
}

// ---------------- launch ----------------
extern "C" void kernel_launch(void* const* d_in, const int* in_sizes, int n_in,
                              void* d_out, int out_size)
{
    const float* x  = (const float*)d_in[0];
    const float* kq = (const float*)d_in[3];
    const float* kk = (const float*)d_in[4];
    const float* kv = (const float*)d_in[5];
    const float* gq = (const float*)d_in[6];
    const float* bq = (const float*)d_in[7];
    const float* mq = (const float*)d_in[8];
    const float* vq = (const float*)d_in[9];
    const float* gk = (const float*)d_in[10];
    const float* bk = (const float*)d_in[11];
    const float* mk = (const float*)d_in[12];
    const float* vk = (const float*)d_in[13];
    const float* gv = (const float*)d_in[14];
    const float* bv = (const float*)d_in[15];
    const float* mv = (const float*)d_in[16];
    const float* vv = (const float*)d_in[17];
    const float* Wq = (const float*)d_in[18];
    const float* Wk = (const float*)d_in[19];
    const float* Wv = (const float*)d_in[20];
    const float* Wo = (const float*)d_in[21];
    const float* bo = (const float*)d_in[22];
    float* out = (float*)d_out;

    float *qin, *kin, *vin, *qh, *vh, *att;
    uint32_t *khi, *klo, *vthi, *vtlo;
    cudaGetSymbolAddress((void**)&qin, g_qin);
    cudaGetSymbolAddress((void**)&kin, g_kin);
    cudaGetSymbolAddress((void**)&vin, g_vin);
    cudaGetSymbolAddress((void**)&qh,  g_q);
    cudaGetSymbolAddress((void**)&vh,  g_v);
    cudaGetSymbolAddress((void**)&att, g_att);
    cudaGetSymbolAddress((void**)&khi, g_khi);
    cudaGetSymbolAddress((void**)&klo, g_klo);
    cudaGetSymbolAddress((void**)&vthi, g_vthi);
    cudaGetSymbolAddress((void**)&vtlo, g_vtlo);

    prep_kernel<<<(M_*C_ + 255)/256, 256>>>(x, kq, kk, kv,
                                            gq, bq, mq, vq,
                                            gk, bk, mk, vk,
                                            gv, bv, mv, vv);

    dim3 gq3((M_ + 127)/128, C_/64, 3);
    gemm_qkv<<<gq3, 256>>>(qin, kin, vin, Wq, Wk, Wv, qh, vh, khi, klo);

    vpack<<<dim3(TP/32, DH/32, BH_), 256>>>(vh, vthi, vtlo);

    cudaFuncSetAttribute(attn_tc2,
                         cudaFuncAttributeMaxDynamicSharedMemorySize, ATTN_SMEM);
    attn_tc2<<<dim3((T_ + QB - 1)/QB, BH_), 256, ATTN_SMEM>>>(qh, khi, klo, vthi, vtlo, att);

    gemm_o<<<dim3((M_ + 127)/128, C_/64), 256>>>(att, Wo, bo, out);
}